// round 4
// baseline (speedup 1.0000x reference)
#include <cuda_runtime.h>
#include <cstdint>

// Problem constants
#define BB    32
#define CC    16
#define NNODE 64
#define TLEN  4096
#define OUTD  16
#define TTILE 128

typedef unsigned long long u64;

// Precomputed, f32x2-SPLATTED M: g_Mdup[(o*64+j)*64 + i] = (m, m) packed in u64,
// where m = sum_n U[i,n]*theta[n,o]*U[j,n]. 512 KB, L2-resident.
__device__ u64 g_Mdup[OUTD * NNODE * NNODE];

// ---------------------------------------------------------------------------
// Kernel 1: precompute splatted M. 65536 elements, 64-term sum each. Trivial.
// ---------------------------------------------------------------------------
__global__ void compute_M_kernel(const float* __restrict__ U,
                                 const float* __restrict__ theta) {
    int idx = blockIdx.x * 256 + threadIdx.x;   // 0..65535
    int o = idx >> 12;
    int j = (idx >> 6) & 63;
    int i = idx & 63;
    float acc = 0.f;
#pragma unroll
    for (int n = 0; n < 64; ++n) {
        acc += U[i * 64 + n] * theta[n * 16 + o] * U[j * 64 + n];
    }
    unsigned ui = __float_as_uint(acc);
    g_Mdup[idx] = ((u64)ui << 32) | (u64)ui;    // (m, m) splat
}

// ---------------------------------------------------------------------------
// Kernel 2: fused channel-sum + 16x (64x64 @ 64x128) GEMM, pure FFMA2 inner loop.
// Grid: (T/128, B). Block: 256 threads, 2 CTAs/SM.
// Dynamic smem layout:
//   [0, 32768)      xs4: channel-summed x tile, float4 [64 rows][32 float4]
//   [32768, 73728)  mss: splatted M_o, u64, rg-block layout:
//                   value (j, i) at u64 index (j*8 + (i>>3))*10 + (i&7)
//                   (8 data u64 + 2 pad u64 per rg-block -> 80B stride, so the
//                   4 distinct rg addresses in a warp are bank-conflict-free)
// ---------------------------------------------------------------------------
__global__ void __launch_bounds__(256, 2)
spectral_main_kernel(const float* __restrict__ x, float* __restrict__ y) {
    extern __shared__ char smem_raw[];
    float4* xs4 = (float4*)smem_raw;                 // 32 KB
    u64*    mss = (u64*)(smem_raw + 32768);          // 40 KB

    const int tid = threadIdx.x;
    const int b   = blockIdx.y;
    const int t0  = blockIdx.x * TTILE;

    // ---- Phase 1: channel sum into smem: xs[n][tl] = sum_c x[b,c,n,t0+tl]
#pragma unroll
    for (int k = 0; k < 8; ++k) {
        int eid = tid + k * 256;          // 0..2047
        int n   = eid >> 5;               // 0..63
        int tc  = eid & 31;               // float4 column 0..31
        const float4* px =
            (const float4*)(x + ((size_t)b * CC * NNODE + n) * TLEN + t0) + tc;
        float4 s = make_float4(0.f, 0.f, 0.f, 0.f);
#pragma unroll
        for (int c = 0; c < CC; ++c) {
            float4 v = px[(size_t)c * (NNODE * (TLEN / 4))];
            s.x += v.x; s.y += v.y; s.z += v.z; s.w += v.w;
        }
        xs4[eid] = s;
    }

    // Thread tile mapping: 8 row-groups (rg) x 32 t-groups (tg).
    // Warp covers 4 rg x 8 tg: m-loads broadcast (8 lanes/addr), x-loads span
    // one contiguous 128B window.
    const int w  = tid >> 5;
    const int l  = tid & 31;
    const int rg = ((w >> 2) << 2) + (l >> 3);   // 0..7  -> rows rg*8 .. rg*8+7
    const int tg = ((w & 3) << 3) + (l & 7);     // 0..31 -> t = tg*4 .. tg*4+3

    for (int o = 0; o < OUTD; ++o) {
        __syncthreads();   // xs ready (o==0) / previous reads of mss done (o>0)

        // stage splatted M_o (4096 u64 = 32 KB) into rg-block layout
        const ulonglong2* gm2 = (const ulonglong2*)(g_Mdup + o * (NNODE * NNODE));
#pragma unroll
        for (int k = 0; k < 8; ++k) {
            int e = tid + k * 256;            // ulonglong2 index 0..2047
            ulonglong2 v = gm2[e];
            int u  = e << 1;                  // u64 index in (j,i) space
            int jj = u >> 6;
            int ii = u & 63;
            *(ulonglong2*)&mss[(jj * 8 + (ii >> 3)) * 10 + (ii & 7)] = v;
        }
        __syncthreads();

        // 8 rows x 4 t as packed f32x2 accumulators
        u64 acc[8][2];
#pragma unroll
        for (int r = 0; r < 8; ++r) { acc[r][0] = 0ull; acc[r][1] = 0ull; }

#pragma unroll 4
        for (int j = 0; j < NNODE; ++j) {
            // x: xs[j][tg*4 .. tg*4+3] as one LDS.128 (two f32x2 lanes)
            ulonglong2 xv = *(const ulonglong2*)&xs4[j * 32 + tg];
            // m: 8 pre-splatted (m,m) pairs for rows rg*8..rg*8+7, 4x LDS.128,
            // conflict-free across the warp's 4 rg values (80B stride)
            const u64* mrow = &mss[(j * 8 + rg) * 10];
            ulonglong2 ma = *(const ulonglong2*)(mrow + 0);
            ulonglong2 mb = *(const ulonglong2*)(mrow + 2);
            ulonglong2 mc = *(const ulonglong2*)(mrow + 4);
            ulonglong2 me = *(const ulonglong2*)(mrow + 6);
            u64 mm[8] = {ma.x, ma.y, mb.x, mb.y, mc.x, mc.y, me.x, me.y};
#pragma unroll
            for (int r = 0; r < 8; ++r) {
                asm("fma.rn.f32x2 %0, %1, %2, %0;"
                    : "+l"(acc[r][0]) : "l"(xv.x), "l"(mm[r]));
                asm("fma.rn.f32x2 %0, %1, %2, %0;"
                    : "+l"(acc[r][1]) : "l"(xv.y), "l"(mm[r]));
            }
        }

        // store: y[b,o,i,t0+tg*4 .. +3], one STG.128 per row, coalesced across tg
        float* ybase = y + (((size_t)b * OUTD + o) * NNODE) * TLEN + t0 + tg * 4;
#pragma unroll
        for (int r = 0; r < 8; ++r) {
            int i = rg * 8 + r;
            ulonglong2 v;
            v.x = acc[r][0];
            v.y = acc[r][1];
            *(ulonglong2*)(ybase + (size_t)i * TLEN) = v;
        }
    }
}

// ---------------------------------------------------------------------------
// kernel_launch: graph-capturable, allocation-free.
// Inputs (metadata order): x (B,C,N,T) f32, U (N,N) f32, theta (N,OUT) f32.
// Output: y (B,OUT,N,T) f32.
// ---------------------------------------------------------------------------
extern "C" void kernel_launch(void* const* d_in, const int* in_sizes, int n_in,
                              void* d_out, int out_size) {
    const float* x     = (const float*)d_in[0];
    const float* U     = (const float*)d_in[1];
    const float* theta = (const float*)d_in[2];
    float* y = (float*)d_out;

    // 72 KB dynamic smem (attribute set is idempotent, not a stream op)
    cudaFuncSetAttribute(spectral_main_kernel,
                         cudaFuncAttributeMaxDynamicSharedMemorySize, 73728);

    compute_M_kernel<<<256, 256>>>(U, theta);
    spectral_main_kernel<<<dim3(TLEN / TTILE, BB), 256, 73728>>>(x, y);
}